// round 12
// baseline (speedup 1.0000x reference)
#include <cuda_runtime.h>
#include <cstdint>
#include <cstddef>

#define DIM   8192
#define BATCH 8
#define TOPK  60
#define CAND_CAP 3072

// ---------------- scratch (device globals; no allocation allowed) ----------
__device__ float g_act1 [BATCH * DIM];
__device__ float g_act2 [BATCH * DIM];
__device__ float g_vals [BATCH * 64];
__device__ int   g_idx  [BATCH * 64];
__device__ int   g_hist1[BATCH * 256];
__device__ int   g_hist2[BATCH * 256];

typedef unsigned long long u64;

__device__ __forceinline__ void fma2(u64& d, u64 a, u64 b) {
    asm volatile("fma.rn.f32x2 %0, %1, %2, %0;" : "+l"(d) : "l"(a), "l"(b));
}
__device__ __forceinline__ float sigmoidf_(float x) {
    return 1.0f / (1.0f + __expf(-x));
}
__device__ __forceinline__ float pairsum(u64 a) {
    return __uint_as_float((unsigned)(a & 0xffffffffull)) +
           __uint_as_float((unsigned)(a >> 32));
}
// order-preserving float->uint transform (uint order == float order)
__device__ __forceinline__ unsigned fkey(float v) {
    unsigned b = __float_as_uint(v);
    return b ^ (unsigned)(((int)b >> 31) | 0x80000000);
}
__device__ __forceinline__ float funkey(unsigned k) {
    unsigned b = (k & 0x80000000u) ? (k ^ 0x80000000u) : ~k;
    return __uint_as_float(b);
}

// ---------------------------------------------------------------------------
__global__ void zero_hist_kernel() {
    int t = threadIdx.x;
    if (t < BATCH * 256) { g_hist1[t] = 0; g_hist2[t] = 0; }
}

// ---------------------------------------------------------------------------
// GEMM1 (raw sums) — R9-proven (≈44 us) + fused top-byte histogram epilogue.
// 256 threads (8 warps), 4 rows/warp, 32-row j-tile, grid = 256.
// ---------------------------------------------------------------------------
__global__ __launch_bounds__(256, 2) void gemm1_kernel(
    const float* __restrict__ sdr,
    const float* __restrict__ syn,
    float* __restrict__ out)
{
    __shared__ float4 s_sdr[BATCH * 256];     // 8 x 1024 floats = 32 KB

    const int tid  = threadIdx.x;
    const int warp = tid >> 5;
    const int lane = tid & 31;
    const int jBase = blockIdx.x * 32 + warp * 4;

    const float4* __restrict__ sdr4 = reinterpret_cast<const float4*>(sdr);
    const float4* __restrict__ syn4 = reinterpret_cast<const float4*>(syn);
    const int ROW4 = DIM / 4;                 // 2048 float4 per row

    u64 acc[4][BATCH];
#pragma unroll
    for (int r = 0; r < 4; ++r)
#pragma unroll
        for (int b = 0; b < BATCH; ++b) acc[r][b] = 0ull;

    for (int c = 0; c < 8; ++c) {             // 8 chunks of 1024 floats
        __syncthreads();
#pragma unroll
        for (int u = 0; u < 8; ++u) {
            int e = tid + u * 256;            // 0..2047
            int b = e >> 8, q = e & 255;
            s_sdr[b * 256 + q] = sdr4[(size_t)b * ROW4 + c * 256 + q];
        }
        __syncthreads();

        float4 w[4];
#pragma unroll
        for (int r = 0; r < 4; ++r)
            w[r] = syn4[(size_t)(jBase + r) * ROW4 + c * 256 + lane];

#pragma unroll 1
        for (int it = 0; it < 8; ++it) {      // 256 float4 / 32 lanes
            float4 wn[4];
            if (it < 7) {
#pragma unroll
                for (int r = 0; r < 4; ++r)
                    wn[r] = syn4[(size_t)(jBase + r) * ROW4 + c * 256 + (it + 1) * 32 + lane];
            }
            const int pos = it * 32 + lane;
#pragma unroll
            for (int b = 0; b < BATCH; ++b) {
                float4 s = s_sdr[b * 256 + pos];
                u64 sx = *reinterpret_cast<u64*>(&s.x);
                u64 sz = *reinterpret_cast<u64*>(&s.z);
#pragma unroll
                for (int r = 0; r < 4; ++r) {
                    fma2(acc[r][b], sx, *reinterpret_cast<u64*>(&w[r].x));
                    fma2(acc[r][b], sz, *reinterpret_cast<u64*>(&w[r].z));
                }
            }
            if (it < 7) {
#pragma unroll
                for (int r = 0; r < 4; ++r) w[r] = wn[r];
            }
        }
    }

#pragma unroll
    for (int r = 0; r < 4; ++r) {
#pragma unroll
        for (int b = 0; b < BATCH; ++b) {
            float v = pairsum(acc[r][b]);
#pragma unroll
            for (int o = 16; o > 0; o >>= 1)
                v += __shfl_xor_sync(0xffffffffu, v, o);
            if (lane == r * 8 + b) {
                out[(size_t)b * DIM + jBase + r] = v;
                atomicAdd(&g_hist1[b * 256 + (int)(fkey(v) >> 24)], 1);
            }
        }
    }
}

// ---------------------------------------------------------------------------
// Exact top-k selection using the precomputed top-byte histogram.
// One block (1024 threads) per row. Scan hist -> boundary byte `digit` + kk.
// Elements with byte > digit are selected outright; elements with byte ==
// digit (~200, cap 3072 with >3x margin vs worst-case analysis) get an exact
// O(np) rank under (value desc, index asc) — matches jax.lax.top_k ties.
// Sigmoid applied on output only (monotone => same selection).
// ---------------------------------------------------------------------------
__global__ __launch_bounds__(1024) void topk_select(
    const float* __restrict__ act,
    const int*   __restrict__ ghist,
    float* __restrict__ vals,     // compact sigmoid'd values (or nullptr)
    int*   __restrict__ idxs,     // compact indices (or nullptr)
    float* __restrict__ dense)    // dense zero-filled sigmoid'd row (or nullptr)
{
    __shared__ unsigned ck[CAND_CAP];
    __shared__ int      cg[CAND_CAP];
    __shared__ int s_digit, s_kk, s_np, s_pos;

    const int row  = blockIdx.x;
    const int tid  = threadIdx.x;
    const int warp = tid >> 5;
    const int lane = tid & 31;
    const float* __restrict__ arow = act + (size_t)row * DIM;

    // load keys (registers)
    unsigned key[8];
#pragma unroll
    for (int u = 0; u < 8; ++u)
        key[u] = fkey(arow[tid + u * 1024]);

    if (tid == 0) { s_np = 0; s_pos = 0; }

    // warp 0: top-down scan of the 256-bin histogram for this row
    if (warp == 0) {
        const int base = 255 - lane * 8;
        int cnt[8]; int local = 0;
#pragma unroll
        for (int j = 0; j < 8; ++j) { cnt[j] = ghist[row * 256 + base - j]; local += cnt[j]; }
        int incl = local;
#pragma unroll
        for (int o = 1; o < 32; o <<= 1) {
            int v = __shfl_up_sync(0xffffffffu, incl, o);
            if (lane >= o) incl += v;
        }
        const int excl = incl - local;
        if (excl < TOPK && TOPK <= incl) {    // exactly one lane
            int run = excl; int found = 0;
#pragma unroll
            for (int j = 0; j < 8; ++j) {
                if (!found && run + cnt[j] >= TOPK) {
                    s_digit = base - j;
                    s_kk = TOPK - run;
                    found = 1;
                }
                run += cnt[j];
            }
        }
    }

    // zero-fill dense row while the scan completes
    if (dense) {
        float4* d4 = reinterpret_cast<float4*>(dense + (size_t)row * DIM);
#pragma unroll
        for (int u = 0; u < 2; ++u)
            d4[tid + u * 1024] = make_float4(0.f, 0.f, 0.f, 0.f);
    }
    __syncthreads();

    const unsigned digit = (unsigned)s_digit;
    const int kk = s_kk;

    // classify: byte > digit -> selected; byte == digit -> candidate
#pragma unroll
    for (int u = 0; u < 8; ++u) {
        const unsigned by = key[u] >> 24;
        const int gi = tid + u * 1024;
        if (by > digit) {
            float sv = sigmoidf_(funkey(key[u]));
            if (vals) {
                int p = atomicAdd(&s_pos, 1);
                vals[row * 64 + p] = sv;
                idxs[row * 64 + p] = gi;
            }
            if (dense) dense[(size_t)row * DIM + gi] = sv;
        } else if (by == digit) {
            int q = atomicAdd(&s_np, 1);
            if (q < CAND_CAP) { ck[q] = key[u]; cg[q] = gi; }
        }
    }
    __syncthreads();

    const int np = (s_np < CAND_CAP) ? s_np : CAND_CAP;

    // exact rank-select among candidates (value desc, index asc)
    for (int c = tid; c < np; c += 1024) {
        const unsigned kc = ck[c];
        const int gc = cg[c];
        int rank = 0;
        for (int i = 0; i < np; ++i) {
            unsigned ki = ck[i];
            rank += (ki > kc) || (ki == kc && cg[i] < gc);
        }
        if (rank < kk) {
            float sv = sigmoidf_(funkey(kc));
            if (vals) {
                int p = atomicAdd(&s_pos, 1);
                vals[row * 64 + p] = sv;
                idxs[row * 64 + p] = gc;
            }
            if (dense) dense[(size_t)row * DIM + gc] = sv;
        }
    }
}

// ---------------------------------------------------------------------------
// GEMM2 (sparse, raw) — R7-proven (≈42 us) + fused histogram epilogue.
// One warp per (j,b): all 60 gathers inside the single 32KB row j.
// ---------------------------------------------------------------------------
__global__ __launch_bounds__(1024) void gemm2_kernel(
    const float* __restrict__ syn,
    const float* __restrict__ vals,
    const int*   __restrict__ idxs,
    float* __restrict__ out)
{
    __shared__ float sv[BATCH][64];
    __shared__ int   si[BATCH][64];

    const int tid = threadIdx.x;
    if (tid < BATCH * 64) {
        int bb = tid >> 6, ss = tid & 63;
        sv[bb][ss] = (ss < TOPK) ? vals[bb * 64 + ss] : 0.0f;
        si[bb][ss] = (ss < TOPK) ? idxs[bb * 64 + ss] : 0;
    }
    __syncthreads();

    const int warp = tid >> 5;
    const int lane = tid & 31;
    const int gw = blockIdx.x * 32 + warp;   // 0..65535
    const int j  = gw >> 3;                  // 0..8191
    const int b  = gw & 7;

    const float* __restrict__ wrow = syn + (size_t)j * DIM;
    float acc = sv[b][lane]      * __ldg(wrow + si[b][lane])
              + sv[b][lane + 32] * __ldg(wrow + si[b][lane + 32]);

#pragma unroll
    for (int o = 16; o > 0; o >>= 1)
        acc += __shfl_xor_sync(0xffffffffu, acc, o);
    if (lane == 0) {
        out[(size_t)b * DIM + j] = acc;
        atomicAdd(&g_hist2[b * 256 + (int)(fkey(acc) >> 24)], 1);
    }
}

// ---------------------------------------------------------------------------
extern "C" void kernel_launch(void* const* d_in, const int* in_sizes, int n_in,
                              void* d_out, int out_size)
{
    const float* sdr = (const float*)d_in[0];
    const float* syn = (const float*)d_in[1];
    // steps=2, top_k=60 fixed by setup_inputs (hardcoded)

    float *act1, *act2, *vals;
    int *idx, *h1, *h2;
    cudaGetSymbolAddress((void**)&act1, g_act1);
    cudaGetSymbolAddress((void**)&act2, g_act2);
    cudaGetSymbolAddress((void**)&vals, g_vals);
    cudaGetSymbolAddress((void**)&idx,  g_idx);
    cudaGetSymbolAddress((void**)&h1,   g_hist1);
    cudaGetSymbolAddress((void**)&h2,   g_hist2);

    zero_hist_kernel<<<2, 1024>>>();
    // step 1: dense GEMM (raw sums + hist) -> exact top-60 -> compact lists
    gemm1_kernel<<<DIM / 32, 256>>>(sdr, syn, act1);
    topk_select<<<BATCH, 1024>>>(act1, h1, vals, idx, nullptr);
    // step 2: sparse GEMM (raw sums + hist) -> exact top-60 -> dense output
    gemm2_kernel<<<(DIM * BATCH) / 32, 1024>>>(syn, vals, idx, act2);
    topk_select<<<BATCH, 1024>>>(act2, h2, nullptr, nullptr, (float*)d_out);
}

// round 15
// speedup vs baseline: 1.3021x; 1.3021x over previous
#include <cuda_runtime.h>
#include <cstdint>
#include <cstddef>

#define DIM   8192
#define BATCH 8
#define TOPK  60
#define CAND_CAP 3072
#define C2_CAP   512

// ---------------- scratch (device globals; no allocation allowed) ----------
__device__ float g_act1 [BATCH * DIM];
__device__ float g_act2 [BATCH * DIM];
__device__ float g_vals [BATCH * 64];
__device__ int   g_idx  [BATCH * 64];
__device__ int   g_hist1[BATCH * 256];
__device__ int   g_hist2[BATCH * 256];

typedef unsigned long long u64;

__device__ __forceinline__ void fma2(u64& d, u64 a, u64 b) {
    asm volatile("fma.rn.f32x2 %0, %1, %2, %0;" : "+l"(d) : "l"(a), "l"(b));
}
__device__ __forceinline__ float sigmoidf_(float x) {
    return 1.0f / (1.0f + __expf(-x));
}
__device__ __forceinline__ float pairsum(u64 a) {
    return __uint_as_float((unsigned)(a & 0xffffffffull)) +
           __uint_as_float((unsigned)(a >> 32));
}
// order-preserving float->uint transform (uint order == float order)
__device__ __forceinline__ unsigned fkey(float v) {
    unsigned b = __float_as_uint(v);
    return b ^ (unsigned)(((int)b >> 31) | 0x80000000);
}
__device__ __forceinline__ float funkey(unsigned k) {
    unsigned b = (k & 0x80000000u) ? (k ^ 0x80000000u) : ~k;
    return __uint_as_float(b);
}
// warp-aggregated slot allocation: one atomic per warp per call
__device__ __forceinline__ int warp_alloc(int* ctr, bool pred, unsigned lanemask_lt_) {
    unsigned mask = __ballot_sync(0xffffffffu, pred);
    int cnt = __popc(mask);
    int leader = __ffs(mask) - 1;
    int base = 0;
    if (cnt) {
        if ((int)(threadIdx.x & 31) == leader) base = atomicAdd(ctr, cnt);
        base = __shfl_sync(0xffffffffu, base, leader);
    }
    return base + __popc(mask & lanemask_lt_);
}

// ---------------------------------------------------------------------------
__global__ void zero_hist_kernel() {
    int t = threadIdx.x;
    if (t < BATCH * 256) { g_hist1[t] = 0; g_hist2[t] = 0; }
}

// ---------------------------------------------------------------------------
// GEMM1 (raw sums) — proven (≈44 us) + fused top-byte histogram epilogue.
// 256 threads (8 warps), 4 rows/warp, 32-row j-tile, grid = 256.
// ---------------------------------------------------------------------------
__global__ __launch_bounds__(256, 2) void gemm1_kernel(
    const float* __restrict__ sdr,
    const float* __restrict__ syn,
    float* __restrict__ out)
{
    __shared__ float4 s_sdr[BATCH * 256];     // 8 x 1024 floats = 32 KB

    const int tid  = threadIdx.x;
    const int warp = tid >> 5;
    const int lane = tid & 31;
    const int jBase = blockIdx.x * 32 + warp * 4;

    const float4* __restrict__ sdr4 = reinterpret_cast<const float4*>(sdr);
    const float4* __restrict__ syn4 = reinterpret_cast<const float4*>(syn);
    const int ROW4 = DIM / 4;                 // 2048 float4 per row

    u64 acc[4][BATCH];
#pragma unroll
    for (int r = 0; r < 4; ++r)
#pragma unroll
        for (int b = 0; b < BATCH; ++b) acc[r][b] = 0ull;

    for (int c = 0; c < 8; ++c) {             // 8 chunks of 1024 floats
        __syncthreads();
#pragma unroll
        for (int u = 0; u < 8; ++u) {
            int e = tid + u * 256;            // 0..2047
            int b = e >> 8, q = e & 255;
            s_sdr[b * 256 + q] = sdr4[(size_t)b * ROW4 + c * 256 + q];
        }
        __syncthreads();

        float4 w[4];
#pragma unroll
        for (int r = 0; r < 4; ++r)
            w[r] = syn4[(size_t)(jBase + r) * ROW4 + c * 256 + lane];

#pragma unroll 1
        for (int it = 0; it < 8; ++it) {      // 256 float4 / 32 lanes
            float4 wn[4];
            if (it < 7) {
#pragma unroll
                for (int r = 0; r < 4; ++r)
                    wn[r] = syn4[(size_t)(jBase + r) * ROW4 + c * 256 + (it + 1) * 32 + lane];
            }
            const int pos = it * 32 + lane;
#pragma unroll
            for (int b = 0; b < BATCH; ++b) {
                float4 s = s_sdr[b * 256 + pos];
                u64 sx = *reinterpret_cast<u64*>(&s.x);
                u64 sz = *reinterpret_cast<u64*>(&s.z);
#pragma unroll
                for (int r = 0; r < 4; ++r) {
                    fma2(acc[r][b], sx, *reinterpret_cast<u64*>(&w[r].x));
                    fma2(acc[r][b], sz, *reinterpret_cast<u64*>(&w[r].z));
                }
            }
            if (it < 7) {
#pragma unroll
                for (int r = 0; r < 4; ++r) w[r] = wn[r];
            }
        }
    }

#pragma unroll
    for (int r = 0; r < 4; ++r) {
#pragma unroll
        for (int b = 0; b < BATCH; ++b) {
            float v = pairsum(acc[r][b]);
#pragma unroll
            for (int o = 16; o > 0; o >>= 1)
                v += __shfl_xor_sync(0xffffffffu, v, o);
            if (lane == r * 8 + b) {
                out[(size_t)b * DIM + jBase + r] = v;
                atomicAdd(&g_hist1[b * 256 + (int)(fkey(v) >> 24)], 1);
            }
        }
    }
}

// ---------------------------------------------------------------------------
// Exact top-k using the precomputed top-byte histogram + in-kernel 2nd-byte
// refinement. One block (1024 threads) per row.
//  1) scan byte hist -> digit, kk.  byte > digit: selected outright.
//  2) collect byte==digit candidates (warp-aggregated; np <= ~2400 < 3072).
//  3) SMEM histogram of candidates' 2nd byte -> digit2, kk2 (np2 ~ tens).
//  4) compact np2 matches, exact O(np2^2) rank (value desc, index asc) —
//     identical to jax.lax.top_k tie order. Exact fallback if np2 > 512.
// Sigmoid applied on outputs only (monotone => same selection).
// ---------------------------------------------------------------------------
__global__ __launch_bounds__(1024) void topk_select(
    const float* __restrict__ act,
    const int*   __restrict__ ghist,
    float* __restrict__ vals,     // compact sigmoid'd values (or nullptr)
    int*   __restrict__ idxs,     // compact indices (or nullptr)
    float* __restrict__ dense)    // dense zero-filled sigmoid'd row (or nullptr)
{
    __shared__ unsigned ck[CAND_CAP];         // 12 KB
    __shared__ int      cg[CAND_CAP];         // 12 KB
    __shared__ int      h2[16][256];          // 16 KB, warp-private x16
    __shared__ unsigned c2k[C2_CAP];
    __shared__ int      c2g[C2_CAP];
    __shared__ int s_digit, s_kk, s_digit2, s_kk2, s_np, s_np2, s_pos;

    const int row  = blockIdx.x;
    const int tid  = threadIdx.x;
    const int warp = tid >> 5;
    const int lane = tid & 31;
    const unsigned lml = (1u << lane) - 1u;
    const float* __restrict__ arow = act + (size_t)row * DIM;

    unsigned key[8];
#pragma unroll
    for (int u = 0; u < 8; ++u)
        key[u] = fkey(arow[tid + u * 1024]);

    if (tid == 0) { s_np = 0; s_np2 = 0; s_pos = 0; }
    // zero 2nd-byte hist: 16*256 = 4096 ints
#pragma unroll
    for (int u = 0; u < 4; ++u)
        (&h2[0][0])[tid + u * 1024] = 0;

    // warp 0: top-down scan of the global 256-bin histogram for this row
    if (warp == 0) {
        const int base = 255 - lane * 8;
        int cnt[8]; int local = 0;
#pragma unroll
        for (int j = 0; j < 8; ++j) { cnt[j] = ghist[row * 256 + base - j]; local += cnt[j]; }
        int incl = local;
#pragma unroll
        for (int o = 1; o < 32; o <<= 1) {
            int v = __shfl_up_sync(0xffffffffu, incl, o);
            if (lane >= o) incl += v;
        }
        const int excl = incl - local;
        if (excl < TOPK && TOPK <= incl) {
            int run = excl; int found = 0;
#pragma unroll
            for (int j = 0; j < 8; ++j) {
                if (!found && run + cnt[j] >= TOPK) {
                    s_digit = base - j;
                    s_kk = TOPK - run;
                    found = 1;
                }
                run += cnt[j];
            }
        }
    }
    if (dense) {
        float4* d4 = reinterpret_cast<float4*>(dense + (size_t)row * DIM);
#pragma unroll
        for (int u = 0; u < 2; ++u)
            d4[tid + u * 1024] = make_float4(0.f, 0.f, 0.f, 0.f);
    }
    __syncthreads();

    const unsigned digit = (unsigned)s_digit;
    const int kk = s_kk;

    // classify; emit sure-selects; collect boundary-byte candidates
#pragma unroll
    for (int u = 0; u < 8; ++u) {
        const unsigned by = key[u] >> 24;
        const int gi = tid + u * 1024;
        if (by > digit) {
            float svv = sigmoidf_(funkey(key[u]));
            if (vals) {
                int p = atomicAdd(&s_pos, 1);
                vals[row * 64 + p] = svv;
                idxs[row * 64 + p] = gi;
            }
            if (dense) dense[(size_t)row * DIM + gi] = svv;
        }
        bool cand = (by == digit);
        int q = warp_alloc(&s_np, cand, lml);
        if (cand && q < CAND_CAP) {
            ck[q] = key[u]; cg[q] = gi;
            atomicAdd(&h2[warp & 15][(key[u] >> 16) & 255], 1);
        }
    }
    __syncthreads();

    const int np = (s_np < CAND_CAP) ? s_np : CAND_CAP;

    // reduce 16 hist copies and scan for 2nd-byte boundary
    if (tid < 256) {
        int s = 0;
#pragma unroll
        for (int w = 0; w < 16; ++w) s += h2[w][tid];
        h2[0][tid] = s;
    }
    __syncthreads();
    if (warp == 0) {
        const int base = 255 - lane * 8;
        int cnt[8]; int local = 0;
#pragma unroll
        for (int j = 0; j < 8; ++j) { cnt[j] = h2[0][base - j]; local += cnt[j]; }
        int incl = local;
#pragma unroll
        for (int o = 1; o < 32; o <<= 1) {
            int v = __shfl_up_sync(0xffffffffu, incl, o);
            if (lane >= o) incl += v;
        }
        const int excl = incl - local;
        if (excl < kk && kk <= incl) {
            int run = excl; int found = 0;
#pragma unroll
            for (int j = 0; j < 8; ++j) {
                if (!found && run + cnt[j] >= kk) {
                    s_digit2 = base - j;
                    s_kk2 = kk - run;
                    found = 1;
                }
                run += cnt[j];
            }
        }
    }
    __syncthreads();

    const unsigned digit2 = (unsigned)s_digit2;
    const int kk2 = s_kk2;

    // candidates with 2nd byte > digit2: selected outright; == : compact
    for (int c = tid; c < np; c += 1024) {
        const unsigned kc = ck[c];
        const unsigned b2 = (kc >> 16) & 255;
        if (b2 > digit2) {
            float svv = sigmoidf_(funkey(kc));
            const int gc = cg[c];
            if (vals) {
                int p = atomicAdd(&s_pos, 1);
                vals[row * 64 + p] = svv;
                idxs[row * 64 + p] = gc;
            }
            if (dense) dense[(size_t)row * DIM + gc] = svv;
        } else if (b2 == digit2) {
            int q = atomicAdd(&s_np2, 1);
            if (q < C2_CAP) { c2k[q] = kc; c2g[q] = cg[c]; }
        }
    }
    __syncthreads();

    const int np2 = s_np2;

    if (np2 <= C2_CAP) {
        // exact rank among the tiny boundary set
        for (int c = tid; c < np2; c += 1024) {
            const unsigned kc = c2k[c];
            const int gc = c2g[c];
            int rank = 0;
            for (int i = 0; i < np2; ++i) {
                unsigned ki = c2k[i];
                rank += (ki > kc) || (ki == kc && c2g[i] < gc);
            }
            if (rank < kk2) {
                float svv = sigmoidf_(funkey(kc));
                if (vals) {
                    int p = atomicAdd(&s_pos, 1);
                    vals[row * 64 + p] = svv;
                    idxs[row * 64 + p] = gc;
                }
                if (dense) dense[(size_t)row * DIM + gc] = svv;
            }
        }
    } else {
        // exact slow path (degenerate clustering): rank over full cand list
        for (int c = tid; c < np; c += 1024) {
            const unsigned kc = ck[c];
            if (((kc >> 16) & 255) != digit2) continue;
            const int gc = cg[c];
            int rank = 0;
            for (int i = 0; i < np; ++i) {
                unsigned ki = ck[i];
                if (((ki >> 16) & 255) != digit2) continue;
                rank += (ki > kc) || (ki == kc && cg[i] < gc);
            }
            if (rank < kk2) {
                float svv = sigmoidf_(funkey(kc));
                if (vals) {
                    int p = atomicAdd(&s_pos, 1);
                    vals[row * 64 + p] = svv;
                    idxs[row * 64 + p] = gc;
                }
                if (dense) dense[(size_t)row * DIM + gc] = svv;
            }
        }
    }
}

// ---------------------------------------------------------------------------
// GEMM2 (sparse, raw) — proven (36.3 us, DRAM 79%) + fused hist epilogue.
// One warp per (j,b): all 60 gathers inside the single 32KB row j.
// ---------------------------------------------------------------------------
__global__ __launch_bounds__(1024) void gemm2_kernel(
    const float* __restrict__ syn,
    const float* __restrict__ vals,
    const int*   __restrict__ idxs,
    float* __restrict__ out)
{
    __shared__ float sv[BATCH][64];
    __shared__ int   si[BATCH][64];

    const int tid = threadIdx.x;
    if (tid < BATCH * 64) {
        int bb = tid >> 6, ss = tid & 63;
        sv[bb][ss] = (ss < TOPK) ? vals[bb * 64 + ss] : 0.0f;
        si[bb][ss] = (ss < TOPK) ? idxs[bb * 64 + ss] : 0;
    }
    __syncthreads();

    const int warp = tid >> 5;
    const int lane = tid & 31;
    const int gw = blockIdx.x * 32 + warp;   // 0..65535
    const int j  = gw >> 3;                  // 0..8191
    const int b  = gw & 7;

    const float* __restrict__ wrow = syn + (size_t)j * DIM;
    float acc = sv[b][lane]      * __ldg(wrow + si[b][lane])
              + sv[b][lane + 32] * __ldg(wrow + si[b][lane + 32]);

#pragma unroll
    for (int o = 16; o > 0; o >>= 1)
        acc += __shfl_xor_sync(0xffffffffu, acc, o);
    if (lane == 0) {
        out[(size_t)b * DIM + j] = acc;
        atomicAdd(&g_hist2[b * 256 + (int)(fkey(acc) >> 24)], 1);
    }
}

// ---------------------------------------------------------------------------
extern "C" void kernel_launch(void* const* d_in, const int* in_sizes, int n_in,
                              void* d_out, int out_size)
{
    const float* sdr = (const float*)d_in[0];
    const float* syn = (const float*)d_in[1];
    // steps=2, top_k=60 fixed by setup_inputs (hardcoded)

    float *act1, *act2, *vals;
    int *idx, *h1, *h2;
    cudaGetSymbolAddress((void**)&act1, g_act1);
    cudaGetSymbolAddress((void**)&act2, g_act2);
    cudaGetSymbolAddress((void**)&vals, g_vals);
    cudaGetSymbolAddress((void**)&idx,  g_idx);
    cudaGetSymbolAddress((void**)&h1,   g_hist1);
    cudaGetSymbolAddress((void**)&h2,   g_hist2);

    zero_hist_kernel<<<2, 1024>>>();
    // step 1: dense GEMM (raw sums + hist) -> exact top-60 -> compact lists
    gemm1_kernel<<<DIM / 32, 256>>>(sdr, syn, act1);
    topk_select<<<BATCH, 1024>>>(act1, h1, vals, idx, nullptr);
    // step 2: sparse GEMM (raw sums + hist) -> exact top-60 -> dense output
    gemm2_kernel<<<(DIM * BATCH) / 32, 1024>>>(syn, vals, idx, act2);
    topk_select<<<BATCH, 1024>>>(act2, h2, nullptr, nullptr, (float*)d_out);
}